// round 17
// baseline (speedup 1.0000x reference)
#include <cuda_runtime.h>

// Problem constants
#define BI 4
#define SS 1024
#define DM 1024
#define NH 16
#define DH 64
#define MROWS (BI * SS)            // 4096
#define OUT_ELEMS (MROWS * DM)     // 4194304
#define ATTN_ELEMS ((size_t)BI * NH * SS * SS)
#define MASK_ELEMS ((size_t)BI * SS * SS)      // 4194304

// Scratch (device globals; allocation inside kernel_launch is forbidden)
__device__ float g_xq[MROWS * DM];   // tf32-rounded Qin
__device__ float g_xk[MROWS * DM];   // tf32-rounded Kin
__device__ float g_xv[MROWS * DM];   // tf32-rounded Vin
__device__ float g_wq[DM * DM];      // tf32-rounded weights
__device__ float g_wk[DM * DM];
__device__ float g_wv[DM * DM];
__device__ float g_wo[DM * DM];
__device__ float g_q[MROWS * DM];    // projections (tf32-rounded values)
__device__ float g_k[MROWS * DM];
__device__ float g_v[MROWS * DM];
__device__ float g_ctx[MROWS * DM];  // tf32-rounded context
__device__ float g_y[MROWS * DM];    // pre-LN (fp32)
__device__ float g_attn[ATTN_ELEMS]; // only used if attn not in d_out
__device__ unsigned char g_mask8[MASK_ELEMS];  // mask as u8 (canonical form)
__device__ int   g_mask_is_int32;

// ---------------------------------------------------------------------------
// tf32 + cp.async helpers
// ---------------------------------------------------------------------------
__device__ __forceinline__ float f2tf(float x) {
    unsigned u;
    asm("cvt.rna.tf32.f32 %0, %1;" : "=r"(u) : "f"(x));
    return __uint_as_float(u);
}
__device__ __forceinline__ float4 tf32x4(float4 v) {
    return make_float4(f2tf(v.x), f2tf(v.y), f2tf(v.z), f2tf(v.w));
}
__device__ __forceinline__ void cpa16(const void* smem_dst, const void* gmem_src) {
    unsigned d = (unsigned)__cvta_generic_to_shared(smem_dst);
    asm volatile("cp.async.ca.shared.global [%0], [%1], 16;" :: "r"(d), "l"(gmem_src));
}
#define CPC    asm volatile("cp.async.commit_group;")
#define CPW(n) asm volatile("cp.async.wait_group %0;" :: "n"(n))

#define MMA_TF32(d, a, b0, b1) \
    asm volatile("mma.sync.aligned.m16n8k8.row.col.f32.tf32.tf32.f32 " \
                 "{%0,%1,%2,%3}, {%4,%5,%6,%7}, {%8,%9}, {%0,%1,%2,%3};" \
                 : "+f"(d[0]), "+f"(d[1]), "+f"(d[2]), "+f"(d[3]) \
                 : "r"(a[0]), "r"(a[1]), "r"(a[2]), "r"(a[3]), "r"(b0), "r"(b1))

// ---------------------------------------------------------------------------
// Mask dtype detection.
// ---------------------------------------------------------------------------
__global__ void detect_mask_kernel(const unsigned* m) {
    int ok = 1;
    for (int i = threadIdx.x; i < 1024; i += 32)
        if (m[i] > 1u) ok = 0;
    unsigned b = __ballot_sync(0xffffffffu, ok);
    if (threadIdx.x == 0) g_mask_is_int32 = (b == 0xffffffffu) ? 1 : 0;
}

// ---------------------------------------------------------------------------
// Consolidated prep: tf32-round inputs & weights, canonicalize mask to u8.
// ---------------------------------------------------------------------------
__global__ __launch_bounds__(256) void prep_kernel(
    const float* __restrict__ Q, const float* __restrict__ K,
    const float* __restrict__ V,
    const float* __restrict__ Wq, const float* __restrict__ Wk,
    const float* __restrict__ Wv, const float* __restrict__ Wo,
    const void* __restrict__ mask)
{
    const int bid = blockIdx.x;
    if (bid < 12288) {
        const int z = bid >> 12;               // /4096
        const float* s = z == 0 ? Q : z == 1 ? K : V;
        float* d = z == 0 ? g_xq : z == 1 ? g_xk : g_xv;
        size_t i = (size_t)(bid & 4095) * 256 + threadIdx.x;
        ((float4*)d)[i] = tf32x4(((const float4*)s)[i]);
    } else if (bid < 16384) {
        const int t = bid - 12288;
        const int z = t >> 10;                 // /1024
        const float* s = z == 0 ? Wq : z == 1 ? Wk : z == 2 ? Wv : Wo;
        float* d = z == 0 ? g_wq : z == 1 ? g_wk : z == 2 ? g_wv : g_wo;
        size_t i = (size_t)(t & 1023) * 256 + threadIdx.x;
        ((float4*)d)[i] = tf32x4(((const float4*)s)[i]);
    } else {
        size_t i = (size_t)(bid - 16384) * 256 + threadIdx.x;
        uchar4 o;
        if (g_mask_is_int32) {
            int4 v = ((const int4*)mask)[i];
            o = make_uchar4(v.x != 0, v.y != 0, v.z != 0, v.w != 0);
        } else {
            o = ((const uchar4*)mask)[i];
        }
        ((uchar4*)g_mask8)[i] = o;
    }
}

// ---------------------------------------------------------------------------
// 3-stage cp.async pipelined tf32 GEMM body (operands pre-rounded to tf32).
// ---------------------------------------------------------------------------
template<int NT, int MW, int MF, int NF, int BNS>
__device__ __forceinline__ void gemm_pipe(
    const float* __restrict__ A, int lda,
    const float* __restrict__ B, int ldb,
    int K, float* __restrict__ sm,
    float (&acc)[MF][NF][4])
{
    constexpr int NWARP = NT / 32;
    constexpr int BM = MW * MF * 16;
    constexpr int BN = (NWARP / MW) * NF * 8;
    constexpr int STG = BM * 20 + 16 * BNS;
    constexpr int LA = BM * 4 / NT;
    constexpr int LB = BN * 4 / NT;
    const int tid = threadIdx.x;
    const int lane = tid & 31, wid = tid >> 5;
    const int wm = (wid & (MW - 1)) * (MF * 16);
    const int wn = (wid / MW) * (NF * 8);
    const int r = lane >> 2, cq = lane & 3;
    const int nch = K / 16;

    auto issue = [&](int c) {
        float* As = sm + (c % 3) * STG;
        float* Bs = As + BM * 20;
        const int k0 = c * 16;
        #pragma unroll
        for (int i = 0; i < LA; i++) {
            int f = tid + i * NT;
            int m = f >> 2, k4 = (f & 3) << 2;
            cpa16(As + m * 20 + k4, A + (size_t)m * lda + k0 + k4);
        }
        #pragma unroll
        for (int i = 0; i < LB; i++) {
            int f = tid + i * NT;
            int k = f / (BN / 4), n4 = (f % (BN / 4)) << 2;
            cpa16(Bs + k * BNS + n4, B + (size_t)(k0 + k) * ldb + n4);
        }
    };

    issue(0); CPC;
    issue(1); CPC;
    for (int c = 0; c < nch; c++) {
        if (c + 2 < nch) {
            CPW(1);
            __syncthreads();
            issue(c + 2); CPC;
        } else {
            CPW(0);
            __syncthreads();
        }
        const unsigned* As = (const unsigned*)(sm + (c % 3) * STG);
        const unsigned* Bs = As + BM * 20;
        #pragma unroll
        for (int ks = 0; ks < 2; ks++) {
            const int cc = ks * 8 + cq;
            unsigned a[MF][4];
            #pragma unroll
            for (int mf = 0; mf < MF; mf++) {
                const unsigned* p = As + (wm + mf * 16 + r) * 20 + cc;
                a[mf][0] = p[0];
                a[mf][1] = p[8 * 20];
                a[mf][2] = p[4];
                a[mf][3] = p[8 * 20 + 4];
            }
            #pragma unroll
            for (int nf = 0; nf < NF; nf++) {
                const int n = wn + nf * 8 + r;
                unsigned b0 = Bs[cc * BNS + n];
                unsigned b1 = Bs[(cc + 4) * BNS + n];
                #pragma unroll
                for (int mf = 0; mf < MF; mf++) {
                    MMA_TF32(acc[mf][nf], a[mf], b0, b1);
                }
            }
        }
    }
}

#define QKV_SMEM_BYTES  (3 * (128 * 20 + 16 * 136) * 4)   // 56832 (2 CTAs/SM)
#define CTX_SMEM_BYTES  (3 * (256 * 20 + 16 * 72) * 4)    // 75264 (2 CTAs/SM)

// ---------------------------------------------------------------------------
// 1) Fused QKV projections (NN): M=4096, N=1024, K=1024. Grid (8, 32, 3).
// ---------------------------------------------------------------------------
__global__ __launch_bounds__(128, 2) void qkv_gemm(
    const float* __restrict__ bq, const float* __restrict__ bk,
    const float* __restrict__ bv)
{
    extern __shared__ float sm[];
    const float* A; const float* W; const float* bias; float* C;
    if (blockIdx.z == 0)      { A = g_xq; W = g_wq; bias = bq; C = g_q; }
    else if (blockIdx.z == 1) { A = g_xk; W = g_wk; bias = bk; C = g_k; }
    else                      { A = g_xv; W = g_wv; bias = bv; C = g_v; }
    const int bm = blockIdx.y * 128, bn = blockIdx.x * 128;
    float acc[4][8][4] = {};
    gemm_pipe<128, 2, 4, 8, 136>(A + (size_t)bm * DM, DM, W + bn, DM, DM, sm, acc);

    const int lane = threadIdx.x & 31, wid = threadIdx.x >> 5;
    const int wm = (wid & 1) * 64, wn = (wid >> 1) * 64;
    const int r = lane >> 2, cq = lane & 3;
    #pragma unroll
    for (int mf = 0; mf < 4; mf++) {
        #pragma unroll
        for (int nf = 0; nf < 8; nf++) {
            int row = bm + wm + mf * 16 + r;
            int col = bn + wn + nf * 8 + 2 * cq;
            float2 bia = *(const float2*)&bias[col];
            *(float2*)&C[(size_t)row * DM + col] =
                make_float2(f2tf(acc[mf][nf][0] + bia.x), f2tf(acc[mf][nf][1] + bia.y));
            *(float2*)&C[(size_t)(row + 8) * DM + col] =
                make_float2(f2tf(acc[mf][nf][2] + bia.x), f2tf(acc[mf][nf][3] + bia.y));
        }
    }
}

// ---------------------------------------------------------------------------
// 2) FUSED scores + mask + softmax — register-resident scores.
// 512 threads (16 warps, grid 2x8). Each thread keeps its 64 score values in
// registers across all 8 K tiles (sc[8][2][4]); Q fragments hoisted once
// (qa[8][4]). Softmax via quad shuffles + tiny red[32][8] smem. attn written
// to gmem once (tf32). Smem: Q tile + 2-stage K ring + red = ~78 KB.
// ---------------------------------------------------------------------------
#define FUS_SMEM_BYTES ((32 * 68 + 2 * 128 * 68 + 256) * 4)   // 79360

__global__ __launch_bounds__(512) void scores_softmax_kernel(
    float* __restrict__ attn_ext, int use_ext)
{
    extern __shared__ float sm[];
    float* Qs  = sm;                         // [32][68]
    float* Ks  = Qs + 32 * 68;               // 2 stages x [128][68]
    float* red = Ks + 2 * 128 * 68;          // [32][8]
    const int tid = threadIdx.x, lane = tid & 31, wid = tid >> 5;
    const int r = lane >> 2, cq = lane & 3;
    const int bh = blockIdx.y, b = bh >> 4, h = bh & 15;
    const int i0 = blockIdx.x * 32;
    const float* qb = g_q + (size_t)b * SS * DM + h * DH + (size_t)i0 * DM;
    const float* kb = g_k + (size_t)b * SS * DM + h * DH;

    // Q tile 32x64 floats = 512 float4 = 1 per thread
    {
        int m = tid >> 4, k4 = (tid & 15) << 2;
        cpa16(Qs + m * 68 + k4, qb + (size_t)m * DM + k4);
    }
    // K tile 128x64 floats = 2048 float4 = 4 per thread
    auto issueK = [&](int jt) {
        float* Kst = Ks + (jt & 1) * (128 * 68);
        const float* kbj = kb + (size_t)jt * 128 * DM;
        #pragma unroll
        for (int i = 0; i < 4; i++) {
            int f = tid + i * 512;
            int m = f >> 4, k4 = (f & 15) << 2;
            cpa16(Kst + m * 68 + k4, kbj + (size_t)m * DM + k4);
        }
    };
    issueK(0); CPC;

    const int wm = (wid & 1) * 16, wn = (wid >> 1) * 16;
    const int wnid = wid >> 1;
    float sc[8][2][4];
    unsigned qa[8][4];

    for (int jt = 0; jt < 8; jt++) {
        if (jt < 7) { issueK(jt + 1); CPC; CPW(1); }
        else        { CPW(0); }
        __syncthreads();
        if (jt == 0) {
            // Hoist Q fragments (rows wm+r / wm+r+8) into registers once.
            const unsigned* Qu = (const unsigned*)Qs;
            #pragma unroll
            for (int kc = 0; kc < 8; kc++) {
                const unsigned* pa = Qu + (wm + r) * 68 + kc * 8 + cq;
                qa[kc][0] = pa[0]; qa[kc][1] = pa[8 * 68];
                qa[kc][2] = pa[4]; qa[kc][3] = pa[8 * 68 + 4];
            }
        }
        const unsigned* Ku = (const unsigned*)(Ks + (jt & 1) * (128 * 68));
        sc[jt][0][0] = sc[jt][0][1] = sc[jt][0][2] = sc[jt][0][3] = 0.f;
        sc[jt][1][0] = sc[jt][1][1] = sc[jt][1][2] = sc[jt][1][3] = 0.f;
        #pragma unroll
        for (int kc = 0; kc < 8; kc++) {
            const int cc = kc * 8 + cq;
            #pragma unroll
            for (int nf = 0; nf < 2; nf++) {
                const unsigned* pb = Ku + (wn + nf * 8 + r) * 68 + cc;
                MMA_TF32(sc[jt][nf], qa[kc], pb[0], pb[4]);
            }
        }
        __syncthreads();   // protect K stage (jt+1)&1 for next issue
    }

    // --- Softmax over register-resident scores ---
    // Thread rows: row0 = wm+r, row1 = wm+r+8 (local 0..31).
    // Cols of sc[jt][nf][0/1]: jt*128 + wn + nf*8 + 2cq + {0,1} (row0);
    // [2/3] same cols (row1).
    const int row0 = wm + r, row1 = wm + r + 8;
    const size_t mb0 = (size_t)b * SS * SS + (size_t)(i0 + row0) * SS;
    const size_t mb1 = (size_t)b * SS * SS + (size_t)(i0 + row1) * SS;

    float m0 = -3.4e38f, m1 = -3.4e38f;
    #pragma unroll
    for (int jt = 0; jt < 8; jt++) {
        #pragma unroll
        for (int nf = 0; nf < 2; nf++) {
            int col = jt * 128 + wn + nf * 8 + 2 * cq;
            uchar2 u0 = *(const uchar2*)(g_mask8 + mb0 + col);
            uchar2 u1 = *(const uchar2*)(g_mask8 + mb1 + col);
            sc[jt][nf][0] = u0.x ? -1e9f : sc[jt][nf][0] * 0.125f;
            sc[jt][nf][1] = u0.y ? -1e9f : sc[jt][nf][1] * 0.125f;
            sc[jt][nf][2] = u1.x ? -1e9f : sc[jt][nf][2] * 0.125f;
            sc[jt][nf][3] = u1.y ? -1e9f : sc[jt][nf][3] * 0.125f;
            m0 = fmaxf(m0, fmaxf(sc[jt][nf][0], sc[jt][nf][1]));
            m1 = fmaxf(m1, fmaxf(sc[jt][nf][2], sc[jt][nf][3]));
        }
    }
    // quad-reduce (cq lanes share a row)
    #pragma unroll
    for (int o = 1; o < 4; o <<= 1) {
        m0 = fmaxf(m0, __shfl_xor_sync(0xffffffffu, m0, o));
        m1 = fmaxf(m1, __shfl_xor_sync(0xffffffffu, m1, o));
    }
    if (cq == 0) { red[row0 * 8 + wnid] = m0; red[row1 * 8 + wnid] = m1; }
    __syncthreads();
    float M0 = red[row0 * 8 + 0], M1 = red[row1 * 8 + 0];
    #pragma unroll
    for (int i = 1; i < 8; i++) {
        M0 = fmaxf(M0, red[row0 * 8 + i]);
        M1 = fmaxf(M1, red[row1 * 8 + i]);
    }
    __syncthreads();   // all reads of max partials done before sum overwrite

    float s0 = 0.f, s1 = 0.f;
    #pragma unroll
    for (int jt = 0; jt < 8; jt++) {
        #pragma unroll
        for (int nf = 0; nf < 2; nf++) {
            sc[jt][nf][0] = __expf(sc[jt][nf][0] - M0);
            sc[jt][nf][1] = __expf(sc[jt][nf][1] - M0);
            sc[jt][nf][2] = __expf(sc[jt][nf][2] - M1);
            sc[jt][nf][3] = __expf(sc[jt][nf][3] - M1);
            s0 += sc[jt][nf][0] + sc[jt][nf][1];
            s1 += sc[jt][nf][2] + sc[jt][nf][3];
        }
    }
    #pragma unroll
    for (int o = 1; o < 4; o <<= 1) {
        s0 += __shfl_xor_sync(0xffffffffu, s0, o);
        s1 += __shfl_xor_sync(0xffffffffu, s1, o);
    }
    if (cq == 0) { red[row0 * 8 + wnid] = s0; red[row1 * 8 + wnid] = s1; }
    __syncthreads();
    float S0 = 0.f, S1 = 0.f;
    #pragma unroll
    for (int i = 0; i < 8; i++) {
        S0 += red[row0 * 8 + i];
        S1 += red[row1 * 8 + i];
    }
    float inv0 = 1.0f / S0, inv1 = 1.0f / S1;

    float* attn = use_ext ? attn_ext : g_attn;
    const size_t ab0 = (size_t)bh * SS * SS + (size_t)(i0 + row0) * SS;
    const size_t ab1 = (size_t)bh * SS * SS + (size_t)(i0 + row1) * SS;
    #pragma unroll
    for (int jt = 0; jt < 8; jt++) {
        #pragma unroll
        for (int nf = 0; nf < 2; nf++) {
            int col = jt * 128 + wn + nf * 8 + 2 * cq;
            *(float2*)&attn[ab0 + col] =
                make_float2(f2tf(sc[jt][nf][0] * inv0), f2tf(sc[jt][nf][1] * inv0));
            *(float2*)&attn[ab1 + col] =
                make_float2(f2tf(sc[jt][nf][2] * inv1), f2tf(sc[jt][nf][3] * inv1));
        }
    }
}

// ---------------------------------------------------------------------------
// 3) Context (NN): per bh M=1024, N=64, K=1024. Grid (1, 4, 64). 2 CTAs/SM.
// ---------------------------------------------------------------------------
__global__ __launch_bounds__(256, 2) void context_kernel(const float* __restrict__ attn_ext, int use_ext) {
    extern __shared__ float sm[];
    const int bh = blockIdx.z, b = bh >> 4, h = bh & 15;
    const int bi = blockIdx.y * 256;
    const float* attn = use_ext ? attn_ext : g_attn;
    const float* ab = attn + (size_t)bh * SS * SS + (size_t)bi * SS;
    const float* vb = g_v + (size_t)b * SS * DM + h * DH;
    float acc[4][4][4] = {};
    gemm_pipe<256, 4, 4, 4, 72>(ab, SS, vb, DM, SS, sm, acc);

    const int lane = threadIdx.x & 31, wid = threadIdx.x >> 5;
    const int wm = (wid & 3) * 64, wn = (wid >> 2) * 32;
    const int r = lane >> 2, cq = lane & 3;
    float* cb = g_ctx + (size_t)b * SS * DM + h * DH;
    #pragma unroll
    for (int mf = 0; mf < 4; mf++) {
        #pragma unroll
        for (int nf = 0; nf < 4; nf++) {
            int row = bi + wm + mf * 16 + r;
            int col = wn + nf * 8 + 2 * cq;
            *(float2*)&cb[(size_t)row * DM + col] =
                make_float2(f2tf(acc[mf][nf][0]), f2tf(acc[mf][nf][1]));
            *(float2*)&cb[(size_t)(row + 8) * DM + col] =
                make_float2(f2tf(acc[mf][nf][2]), f2tf(acc[mf][nf][3]));
        }
    }
}

// ---------------------------------------------------------------------------
// 4) Output projection + residual (NN). Grid (8, 32), 128 thr, 2 CTAs/SM.
// ---------------------------------------------------------------------------
__global__ __launch_bounds__(128, 2) void outproj_kernel(
    const float* __restrict__ bo, const float* __restrict__ Qres)
{
    extern __shared__ float sm[];
    const int bm = blockIdx.y * 128, bn = blockIdx.x * 128;
    float acc[4][8][4] = {};
    gemm_pipe<128, 2, 4, 8, 136>(g_ctx + (size_t)bm * DM, DM, g_wo + bn, DM, DM, sm, acc);

    const int lane = threadIdx.x & 31, wid = threadIdx.x >> 5;
    const int wm = (wid & 1) * 64, wn = (wid >> 1) * 64;
    const int r = lane >> 2, cq = lane & 3;
    #pragma unroll
    for (int mf = 0; mf < 4; mf++) {
        #pragma unroll
        for (int nf = 0; nf < 8; nf++) {
            int row = bm + wm + mf * 16 + r;
            int col = bn + wn + nf * 8 + 2 * cq;
            float2 bia = *(const float2*)&bo[col];
            float2 q0 = *(const float2*)&Qres[(size_t)row * DM + col];
            float2 q1 = *(const float2*)&Qres[(size_t)(row + 8) * DM + col];
            *(float2*)&g_y[(size_t)row * DM + col] =
                make_float2(acc[mf][nf][0] + bia.x + q0.x, acc[mf][nf][1] + bia.y + q0.y);
            *(float2*)&g_y[(size_t)(row + 8) * DM + col] =
                make_float2(acc[mf][nf][2] + bia.x + q1.x, acc[mf][nf][3] + bia.y + q1.y);
        }
    }
}

// ---------------------------------------------------------------------------
// 5) LayerNorm over last dim (1024), biased variance, eps 1e-5. Grid 4096x256.
// ---------------------------------------------------------------------------
__global__ __launch_bounds__(256) void ln_kernel(
    const float* __restrict__ gamma, const float* __restrict__ beta,
    float* __restrict__ out)
{
    const float4* row = (const float4*)(g_y + (size_t)blockIdx.x * DM);
    const int t = threadIdx.x, lane = t & 31, w = t >> 5;
    __shared__ float s1[8], s2[8];
    float4 x = row[t];
    float a = x.x + x.y + x.z + x.w;
    float b = x.x * x.x + x.y * x.y + x.z * x.z + x.w * x.w;
    #pragma unroll
    for (int o = 16; o > 0; o >>= 1) {
        a += __shfl_xor_sync(0xffffffffu, a, o);
        b += __shfl_xor_sync(0xffffffffu, b, o);
    }
    if (lane == 0) { s1[w] = a; s2[w] = b; }
    __syncthreads();
    float A = 0.f, B2 = 0.f;
    #pragma unroll
    for (int i = 0; i < 8; i++) { A += s1[i]; B2 += s2[i]; }
    float mean = A * (1.0f / 1024.0f);
    float var = B2 * (1.0f / 1024.0f) - mean * mean;
    float rstd = rsqrtf(var + 1e-5f);
    float4 g = ((const float4*)gamma)[t];
    float4 be = ((const float4*)beta)[t];
    float4 o4;
    o4.x = (x.x - mean) * rstd * g.x + be.x;
    o4.y = (x.y - mean) * rstd * g.y + be.y;
    o4.z = (x.z - mean) * rstd * g.z + be.z;
    o4.w = (x.w - mean) * rstd * g.w + be.w;
    ((float4*)(out + (size_t)blockIdx.x * DM))[t] = o4;
}

// ---------------------------------------------------------------------------
extern "C" void kernel_launch(void* const* d_in, const int* in_sizes, int n_in,
                              void* d_out, int out_size) {
    const float* Qin   = (const float*)d_in[0];
    const void*  mask  = d_in[3];
    const float* Wq    = (const float*)d_in[4];
    const float* bq    = (const float*)d_in[5];
    const float* Wk    = (const float*)d_in[6];
    const float* bk    = (const float*)d_in[7];
    const float* Wv    = (const float*)d_in[8];
    const float* bv    = (const float*)d_in[9];
    const float* Wo    = (const float*)d_in[10];
    const float* bo    = (const float*)d_in[11];
    const float* gamma = (const float*)d_in[12];
    const float* beta  = (const float*)d_in[13];
    float* out = (float*)d_out;

    const int use_ext = (out_size > OUT_ELEMS) ? 1 : 0;
    float* attn_ext = out + OUT_ELEMS;

    cudaFuncSetAttribute(qkv_gemm, cudaFuncAttributeMaxDynamicSharedMemorySize, QKV_SMEM_BYTES);
    cudaFuncSetAttribute(outproj_kernel, cudaFuncAttributeMaxDynamicSharedMemorySize, QKV_SMEM_BYTES);
    cudaFuncSetAttribute(scores_softmax_kernel, cudaFuncAttributeMaxDynamicSharedMemorySize, FUS_SMEM_BYTES);
    cudaFuncSetAttribute(context_kernel, cudaFuncAttributeMaxDynamicSharedMemorySize, CTX_SMEM_BYTES);

    detect_mask_kernel<<<1, 32>>>((const unsigned*)mask);
    prep_kernel<<<dim3(20480), 256>>>(
        Qin, (const float*)d_in[1], (const float*)d_in[2],
        Wq, Wk, Wv, Wo, mask);
    qkv_gemm<<<dim3(8, 32, 3), 128, QKV_SMEM_BYTES>>>(bq, bk, bv);
    scores_softmax_kernel<<<dim3(32, 64), 512, FUS_SMEM_BYTES>>>(attn_ext, use_ext);
    context_kernel<<<dim3(1, 4, 64), 256, CTX_SMEM_BYTES>>>(attn_ext, use_ext);
    outproj_kernel<<<dim3(8, 32), 128, QKV_SMEM_BYTES>>>(bo, Qin);
    ln_kernel<<<dim3(MROWS), 256>>>(gamma, beta, out);
    (void)in_sizes; (void)n_in;
}